// round 16
// baseline (speedup 1.0000x reference)
#include <cuda_runtime.h>
#include <stdint.h>
#include <math.h>

#define BATCH 512
#define OUTF  1024
#define KPOS  256
#define NIDX  4096
#define BTILE 8
#define NBG   64          // batch groups (8 batches each)
#define KQ    16
#define KQLEN 16
#define SLOT  32768       // NIDX * BTILE bytes
#define SMEM_SZ (2 * SLOT + KQLEN * 16)   // 65792 B

// ---- device scratch (no allocations allowed) ----
__device__ uint8_t  g_tab[NIDX * NIDX];           // 16MB compact u8 table
__device__ ushort4  g_w4[(KPOS / 4) * OUTF];      // PRE-SWIZZLED byte offsets [kb][o]
__device__ uint4    g_part[KQ * NBG * OUTF];      // partials [kq][bg][o]: 16MB

// gather address of interleaved entry e (8B granules, swizzled):
// thread c stages w=16c..16c+15 at 128c + 16*(s ^ (c&7)) + 8*(w&1), s=(w&15)>>1
__device__ __forceinline__ uint32_t gaddr(uint32_t e) {
    uint32_t hi = e >> 4;
    uint32_t p  = (e & 15u) >> 1;
    return hi * 128u + 16u * (p ^ (hi & 7u)) + 8u * (e & 1u);
}

// -------- fused pre-pass: detect mode + convert table + prep w offsets ------
__global__ __launch_bounds__(256) void convert_all_kernel(
    const void* __restrict__ table, const int* __restrict__ w_idx) {
    const uint32_t* tw = (const uint32_t*)table;
    int lane = threadIdx.x & 31;
    bool small = true, isf = true;
#pragma unroll
    for (int i = 0; i < 8; i++) {
        uint32_t x = tw[lane + i * 32];
        small = small && (x < 256u);
        float f = __uint_as_float(x);
        isf = isf && (f >= 0.0f) && (f < 256.0f) && (f == truncf(f));
    }
    small = __all_sync(0xFFFFFFFFu, small);
    isf   = __all_sync(0xFFFFFFFFu, isf);
    const int mode = small ? 1 : (isf ? 2 : 0);

    const int t = blockIdx.x * blockDim.x + threadIdx.x;  // 1M threads

    if (t < (KPOS / 4) * OUTF) {
        int kb = t >> 10;
        int o  = t & 1023;
        int4 v = *(const int4*)&w_idx[o * KPOS + kb * 4];
        uint32_t a = (uint32_t)(v.x < 0 ? 0 : (v.x > NIDX - 1 ? NIDX - 1 : v.x));
        uint32_t b = (uint32_t)(v.y < 0 ? 0 : (v.y > NIDX - 1 ? NIDX - 1 : v.y));
        uint32_t c = (uint32_t)(v.z < 0 ? 0 : (v.z > NIDX - 1 ? NIDX - 1 : v.z));
        uint32_t d = (uint32_t)(v.w < 0 ? 0 : (v.w > NIDX - 1 ? NIDX - 1 : v.w));
        g_w4[t] = make_ushort4((uint16_t)gaddr(a), (uint16_t)gaddr(b),
                               (uint16_t)gaddr(c), (uint16_t)gaddr(d));
    }

    uint4 o;
    if (mode == 1) {
        const int4* src = (const int4*)table;
        uint32_t p[4];
#pragma unroll
        for (int s = 0; s < 4; s++) {
            int4 v = src[t * 4 + s];
            p[s] = (uint32_t)(v.x & 255) | ((uint32_t)(v.y & 255) << 8) |
                   ((uint32_t)(v.z & 255) << 16) | ((uint32_t)(v.w & 255) << 24);
        }
        o = make_uint4(p[0], p[1], p[2], p[3]);
    } else if (mode == 2) {
        const float4* src = (const float4*)table;
        uint32_t p[4];
#pragma unroll
        for (int s = 0; s < 4; s++) {
            float4 v = src[t * 4 + s];
            p[s] = (uint32_t)v.x | ((uint32_t)v.y << 8) |
                   ((uint32_t)v.z << 16) | ((uint32_t)v.w << 24);
        }
        o = make_uint4(p[0], p[1], p[2], p[3]);
    } else {
        o = ((const uint4*)table)[t];
    }
    *(uint4*)&g_tab[t * 16] = o;
}

// 8 rows x 16B -> interleaved 8B entries buf[gaddr(w)] via 8x STS.128
__device__ __forceinline__ void transpose_store8(uint8_t* bufp, const uint32_t* sa,
                                                 const uint4* q) {
    const uint32_t* qa = (const uint32_t*)q;   // qa[j*4+cc]
#pragma unroll
    for (int cc = 0; cc < 4; cc++) {
        uint32_t a0 = qa[0 + cc], a1 = qa[4 + cc], a2 = qa[8 + cc],  a3 = qa[12 + cc];
        uint32_t b0 = qa[16 + cc], b1 = qa[20 + cc], b2 = qa[24 + cc], b3 = qa[28 + cc];
        uint32_t t0 = __byte_perm(a0, a1, 0x5140), t1 = __byte_perm(a0, a1, 0x7362);
        uint32_t t2 = __byte_perm(a2, a3, 0x5140), t3 = __byte_perm(a2, a3, 0x7362);
        uint32_t L0 = __byte_perm(t0, t2, 0x5410), L1 = __byte_perm(t0, t2, 0x7632);
        uint32_t L2 = __byte_perm(t1, t3, 0x5410), L3 = __byte_perm(t1, t3, 0x7632);
        uint32_t u0 = __byte_perm(b0, b1, 0x5140), u1 = __byte_perm(b0, b1, 0x7362);
        uint32_t u2 = __byte_perm(b2, b3, 0x5140), u3 = __byte_perm(b2, b3, 0x7362);
        uint32_t H0 = __byte_perm(u0, u2, 0x5410), H1 = __byte_perm(u0, u2, 0x7632);
        uint32_t H2 = __byte_perm(u1, u3, 0x5410), H3 = __byte_perm(u1, u3, 0x7632);
        *(uint4*)(bufp + sa[2 * cc])     = make_uint4(L0, H0, L1, H1);
        *(uint4*)(bufp + sa[2 * cc + 1]) = make_uint4(L2, H2, L3, H3);
    }
}

// -------- main kernel --------
// CTA = 256 thr, 8 batches x 1024 outputs (4/thread) x 16 k's; 3 CTAs/SM.
// 2-slot ring (32KB each), 1 barrier per k: gather k (slot k&1, one LDS.64
// serves all 8 batches), store k+1 (preloaded at k-1 -> full barrier of LDG
// cover), preload k+2.
__global__ __launch_bounds__(256, 3)
void lookup_kernel(const int* __restrict__ in_idx) {
    extern __shared__ __align__(16) uint8_t smem[];
    uint4* iidv = (uint4*)(smem + 2 * SLOT);   // [KQLEN] 8 packed u16 per k

    const int tid = threadIdx.x;
    const int bg  = blockIdx.x >> 4;
    const int kq  = blockIdx.x & 15;
    const int b0  = bg * BTILE;
    const uint32_t c = (uint32_t)tid;

    // stage this chunk's input indices (clamped): tid<128: j=tid>>4, kk=tid&15
    if (tid < 128) {
        int j = tid >> 4, kk = tid & 15;
        int v = in_idx[(b0 + j) * KPOS + kq * KQLEN + kk];
        v = v < 0 ? 0 : (v > NIDX - 1 ? NIDX - 1 : v);
        ((uint16_t*)&iidv[kk])[j] = (uint16_t)v;
    }

    // swizzled store addresses: thread c owns entries w=16c..16c+15
    uint32_t sa[8];
#pragma unroll
    for (int s = 0; s < 8; s++)
        sa[s] = 128u * c + 16u * ((uint32_t)s ^ (c & 7u));

    __syncthreads();

    // ---- prologue: stage k=0 into slot 0, preload q <- k=1 ----
    uint4 q[8];
    {
        uint4 iv = iidv[0];
        uint32_t r[8] = {iv.x & 0xFFFFu, iv.x >> 16, iv.y & 0xFFFFu, iv.y >> 16,
                         iv.z & 0xFFFFu, iv.z >> 16, iv.w & 0xFFFFu, iv.w >> 16};
#pragma unroll
        for (int j = 0; j < 8; j++)
            q[j] = *(const uint4*)(g_tab + (size_t)r[j] * 4096 + 16u * c);
        transpose_store8(smem, sa, q);
        uint4 iv2 = iidv[1];
        uint32_t r2[8] = {iv2.x & 0xFFFFu, iv2.x >> 16, iv2.y & 0xFFFFu, iv2.y >> 16,
                          iv2.z & 0xFFFFu, iv2.z >> 16, iv2.w & 0xFFFFu, iv2.w >> 16};
#pragma unroll
        for (int j = 0; j < 8; j++)
            q[j] = *(const uint4*)(g_tab + (size_t)r2[j] * 4096 + 16u * c);
    }
    __syncthreads();

    uint32_t aLo[4] = {0, 0, 0, 0};   // batches 0,1 per output m
    uint32_t aHi[4] = {0, 0, 0, 0};   // batches 2,3
    uint32_t bLo[4] = {0, 0, 0, 0};   // batches 4,5
    uint32_t bHi[4] = {0, 0, 0, 0};   // batches 6,7

    for (int kb = 0; kb < KQLEN / 4; kb++) {
        const int gkb = kq * (KQLEN / 4) + kb;
        ushort4 w4[4];
#pragma unroll
        for (int m = 0; m < 4; m++)
            w4[m] = g_w4[gkb * OUTF + tid + 256 * m];  // pre-swizzled offsets
        const uint16_t* wv = (const uint16_t*)w4;       // wv[m*4+u]
#pragma unroll
        for (int u = 0; u < 4; u++) {
            const int k = kb * 4 + u;
            // gather k: one LDS.64 per output serves all 8 batches
            const uint8_t* bp = smem + (k & 1) * SLOT;
#pragma unroll
            for (int m = 0; m < 4; m++) {
                uint2 v = *(const uint2*)(bp + wv[m * 4 + u]);
                aLo[m] = __vadd2(aLo[m], __byte_perm(v.x, 0, 0x4140));
                aHi[m] = __vadd2(aHi[m], __byte_perm(v.x, 0, 0x4342));
                bLo[m] = __vadd2(bLo[m], __byte_perm(v.y, 0, 0x4140));
                bHi[m] = __vadd2(bHi[m], __byte_perm(v.y, 0, 0x4342));
            }
            // store k+1 (preloaded at k-1) into the other slot
            if (k + 1 < KQLEN)
                transpose_store8(smem + ((k + 1) & 1) * SLOT, sa, q);
            // preload k+2 (stored at k+1, gathered at k+2)
            if (k + 2 < KQLEN) {
                uint4 iv = iidv[k + 2];
                uint32_t r[8] = {iv.x & 0xFFFFu, iv.x >> 16, iv.y & 0xFFFFu, iv.y >> 16,
                                 iv.z & 0xFFFFu, iv.z >> 16, iv.w & 0xFFFFu, iv.w >> 16};
#pragma unroll
                for (int j = 0; j < 8; j++)
                    q[j] = *(const uint4*)(g_tab + (size_t)r[j] * 4096 + 16u * c);
            }
            __syncthreads();
        }
    }

    // ---- write packed u16 partials, [kq][bg][o] layout: fully coalesced ----
    uint4* pb = &g_part[(uint32_t)kq * (NBG * OUTF) + (uint32_t)bg * OUTF];
#pragma unroll
    for (int m = 0; m < 4; m++)
        pb[tid + 256 * m] = make_uint4(aLo[m], aHi[m], bLo[m], bHi[m]);
}

// -------- reduce: sum 16 k-chunks, dequantize, write 8 batch rows --------
__global__ __launch_bounds__(256)
void reduce_kernel(const float* __restrict__ scale_p,
                   const float* __restrict__ zp_p,
                   float* __restrict__ out) {
    int t  = blockIdx.x * blockDim.x + threadIdx.x;   // 64*1024 threads
    int bg = t >> 10;
    int o  = t & 1023;
    uint32_t S0 = 0, S1 = 0, S2 = 0, S3 = 0;
#pragma unroll
    for (int kq = 0; kq < KQ; kq++) {
        uint4 p = g_part[(uint32_t)kq * (NBG * OUTF) + (uint32_t)bg * OUTF + o];
        S0 = __vadd2(S0, p.x);    // 16 x 4080 = 65280 max, no overflow
        S1 = __vadd2(S1, p.y);
        S2 = __vadd2(S2, p.z);
        S3 = __vadd2(S3, p.w);
    }
    const float scale = *scale_p;
    const float zp    = *zp_p;
    const float bias  = 256.0f * zp;
    int b0 = bg * BTILE;
    out[(b0 + 0) * OUTF + o] = ((float)(S0 & 0xFFFFu) - bias) * scale;
    out[(b0 + 1) * OUTF + o] = ((float)(S0 >> 16)     - bias) * scale;
    out[(b0 + 2) * OUTF + o] = ((float)(S1 & 0xFFFFu) - bias) * scale;
    out[(b0 + 3) * OUTF + o] = ((float)(S1 >> 16)     - bias) * scale;
    out[(b0 + 4) * OUTF + o] = ((float)(S2 & 0xFFFFu) - bias) * scale;
    out[(b0 + 5) * OUTF + o] = ((float)(S2 >> 16)     - bias) * scale;
    out[(b0 + 6) * OUTF + o] = ((float)(S3 & 0xFFFFu) - bias) * scale;
    out[(b0 + 7) * OUTF + o] = ((float)(S3 >> 16)     - bias) * scale;
}

extern "C" void kernel_launch(void* const* d_in, const int* in_sizes, int n_in,
                              void* d_out, int out_size) {
    (void)in_sizes; (void)n_in; (void)out_size;
    const int*   in_idx = (const int*)d_in[0];
    const int*   w_idx  = (const int*)d_in[1];
    const void*  table  = (const void*)d_in[2];
    const float* scale  = (const float*)d_in[3];
    const float* zp     = (const float*)d_in[4];
    float*       outp   = (float*)d_out;

    // Not stream-ordered; safe on every call (incl. during graph capture).
    cudaFuncSetAttribute(lookup_kernel,
                         cudaFuncAttributeMaxDynamicSharedMemorySize, SMEM_SZ);

    convert_all_kernel<<<(NIDX * NIDX / 16) / 256, 256>>>(table, w_idx);
    lookup_kernel<<<NBG * KQ, 256, SMEM_SZ>>>(in_idx);
    reduce_kernel<<<(NBG * OUTF) / 256, 256>>>(scale, zp, outp);
}